// round 16
// baseline (speedup 1.0000x reference)
#include <cuda_runtime.h>
#include <math.h>
#include <stdint.h>

#define B 64
#define S 512
#define H 768
#define K 64

// Scratch
__device__ float g_pooled[3 * B * H];

__device__ __forceinline__ void cp16(void* dst_smem, const void* src) {
    uint32_t d = (uint32_t)__cvta_generic_to_shared(dst_smem);
    asm volatile("cp.async.cg.shared.global [%0], [%1], 16;" :: "r"(d), "l"(src) : "memory");
}
__device__ __forceinline__ void cp_commit() {
    asm volatile("cp.async.commit_group;" ::: "memory");
}
template<int N> __device__ __forceinline__ void cp_wait() {
    asm volatile("cp.async.wait_group %0;" :: "n"(N) : "memory");
}

// ---------------------------------------------------------------------------
// K1: fused scores + softmax + pool. grid (B, 3, 3 htiles of 256), block 256.
// (proven R13 body)
// ---------------------------------------------------------------------------
__global__ void __launch_bounds__(256)
attn_pool_kernel(const float* __restrict__ seq,
                 const int* __restrict__ idx0, const int* __restrict__ len0,
                 const int* __restrict__ idx1, const int* __restrict__ len1,
                 const int* __restrict__ idx2, const int* __restrict__ len2,
                 const float* __restrict__ bc0,
                 const float* __restrict__ bc1,
                 const float* __restrict__ bc2,
                 float* __restrict__ out) {
    int b  = blockIdx.x;
    int t  = blockIdx.y;
    int zt = blockIdx.z;           // h-tile: h0 = zt*256
    const int* idxp = (t == 0) ? idx0 : (t == 1) ? idx1 : idx2;
    const int* lenp = (t == 0) ? len0 : (t == 1) ? len1 : len2;

    __shared__ float4 g0s[192];    // row 0 (768 floats)
    __shared__ float  scr[K];
    __shared__ float  prob[K];
    __shared__ int    sidx[K];

    int tid  = threadIdx.x;
    int wid  = tid >> 5;
    int lane = tid & 31;

    // bias init (layout: rel 64x9 | nov 64x3 | dir 64x3)
    if (b == 0 && t == 0 && zt == 0) {
        for (int i = tid; i < 960; i += 256) {
            float v;
            if (i < 576)      v = bc0[i % 9];
            else if (i < 768) v = bc1[(i - 576) % 3];
            else              v = bc2[(i - 768) % 3];
            out[i] = v;
        }
    }

    int len = lenp[b];
    if (tid < K) sidx[tid] = idxp[b * K + tid];
    __syncthreads();

    const float* seqb = seq + (size_t)b * S * H;
    int h = zt * 256 + tid;

    if (len == 0) {   // fallback: seq[b, 0, :]
        g_pooled[((size_t)t * B + b) * H + h] = seqb[h];
        return;
    }

    int si0 = sidx[0];
    if (tid < 192) g0s[tid] = ((const float4*)(seqb + (size_t)si0 * H))[tid];
    __syncthreads();

    // ---- Phase 1: scores. Warp wid covers j in {8w..8w+7} as pairs (j, j+4).
    for (int p = 0; p < 4; p++) {
        int ja = 8 * wid + p;
        if (ja >= len) break;                 // warp-uniform
        int jb = ja + 4;
        bool dob = (jb < len);
        const float4* ga = (const float4*)(seqb + (size_t)sidx[ja] * H);
        const float4* gb = (const float4*)(seqb + (size_t)sidx[dob ? jb : ja] * H);

        float4 av[6], bv[6];
        if (dob) {
            #pragma unroll
            for (int i = 0; i < 6; i++) { av[i] = ga[lane + 32 * i]; bv[i] = gb[lane + 32 * i]; }
        } else {
            #pragma unroll
            for (int i = 0; i < 6; i++) { av[i] = ga[lane + 32 * i]; bv[i] = make_float4(0,0,0,0); }
        }

        float sa = 0.f, sb = 0.f;
        #pragma unroll
        for (int i = 0; i < 6; i++) {
            float4 g0v = g0s[lane + 32 * i];
            sa += g0v.x * av[i].x + g0v.y * av[i].y
                + g0v.z * av[i].z + g0v.w * av[i].w;
            sb += g0v.x * bv[i].x + g0v.y * bv[i].y
                + g0v.z * bv[i].z + g0v.w * bv[i].w;
        }
        #pragma unroll
        for (int o = 16; o; o >>= 1) {
            sa += __shfl_xor_sync(0xffffffffu, sa, o);
            sb += __shfl_xor_sync(0xffffffffu, sb, o);
        }
        if (lane == 0) {
            scr[ja] = sa;
            if (dob) scr[jb] = sb;
        }
    }
    __syncthreads();

    // ---- Phase 2: masked softmax (warp 0) ----
    if (tid < 32) {
        float sa = (lane      < len) ? scr[lane]      : -1e30f;
        float sb = (lane + 32 < len) ? scr[lane + 32] : -1e30f;
        float m = fmaxf(sa, sb);
        #pragma unroll
        for (int o = 16; o; o >>= 1) m = fmaxf(m, __shfl_xor_sync(0xffffffffu, m, o));
        float ea = (lane      < len) ? expf(sa - m) : 0.f;
        float eb = (lane + 32 < len) ? expf(sb - m) : 0.f;
        float sum = ea + eb;
        #pragma unroll
        for (int o = 16; o; o >>= 1) sum += __shfl_xor_sync(0xffffffffu, sum, o);
        float inv = 1.0f / sum;
        prob[lane]      = ea * inv;
        prob[lane + 32] = eb * inv;
    }
    __syncthreads();

    // ---- Phase 3: weighted sum for this h slice ----
    const float* base = seqb + h;
    float acc = 0.f;
    #pragma unroll 16
    for (int j = 0; j < len; j++) {
        acc += prob[j] * base[(size_t)sidx[j] * H];
    }
    g_pooled[((size_t)t * B + b) * H + h] = acc;
}

// ---------------------------------------------------------------------------
// K2: h = tanh(P @ Wd^T + bd) + fused classifier. dense v8:
//  - grid (24 rtiles of 32, 4 btiles of 16, 3) = 288 blocks x 128 threads
//    -> 2 independent CTAs/SM (decoupled syncs, small convoys)
//  - thread: row = lane, batches 4wid..4wid+3 (4 acc)
//  - per 4kk: 1x W LDS.128 (stride-68 rows, conflict-free) +
//             4x P LDS.128 (broadcast) + 16 FMA
//  - BOTH W and P k-tiles double-buffered via cp.async (28 KB smem/CTA)
// ---------------------------------------------------------------------------
#define WSTR 68
#define PSTR 68
#define KTILE 64
#define DENSE_SMEM ((2 * 32 * WSTR + 2 * 16 * PSTR + 16 * 34) * sizeof(float)) // 28288 B

__global__ void __launch_bounds__(128)
dense_kernel(const float* __restrict__ Wd0, const float* __restrict__ bd0,
             const float* __restrict__ Wd1, const float* __restrict__ bd1,
             const float* __restrict__ Wd2, const float* __restrict__ bd2,
             const float* __restrict__ Wc0,
             const float* __restrict__ Wc1,
             const float* __restrict__ Wc2,
             float* __restrict__ out) {
    extern __shared__ float dsm[];
    float* Ws = dsm;                        // [2][32][WSTR]
    float* Pt = dsm + 2 * 32 * WSTR;        // [2][16][PSTR]
    float* Hs = Pt + 2 * 16 * PSTR;         // [16][34]  (batch-major, 32 rows)

    int t = blockIdx.z;
    const float* Wd = (t == 0) ? Wd0 : (t == 1) ? Wd1 : Wd2;
    const float* bd = (t == 0) ? bd0 : (t == 1) ? bd1 : bd2;
    const float* Wc = (t == 0) ? Wc0 : (t == 1) ? Wc1 : Wc2;
    int nlab   = (t == 0) ? 9 : 3;
    int outoff = (t == 0) ? 0 : (t == 1) ? B * 9 : B * 9 + B * 3;

    int r0 = blockIdx.x * 32;
    int b0 = blockIdx.y * 16;

    int tid  = threadIdx.x;
    int wid  = tid >> 5;      // batches 4wid..4wid+3
    int lane = tid & 31;      // row = lane

    const float* P = g_pooled + (size_t)t * B * H;

    // staging maps (per k-tile):
    //  W: 512 float4, 4/thread: f4id = tid+128i -> r = f4id>>4, c4 = f4id&15
    //  P: 256 float4, 2/thread: f4id = tid+128i -> bb = f4id>>4, c4 = f4id&15
    int sr  = tid >> 4;     // 0..7
    int sc4 = tid & 15;

    // prologue: issue tile 0 (W + P)
    {
        const float* wsrc = Wd + (size_t)(r0 + sr) * H + 4 * sc4;
        #pragma unroll
        for (int i = 0; i < 4; i++)
            cp16(&Ws[(sr + 8 * i) * WSTR + 4 * sc4], wsrc + (size_t)(8 * i) * H);
        const float* psrc = P + (size_t)(b0 + sr) * H + 4 * sc4;
        #pragma unroll
        for (int i = 0; i < 2; i++)
            cp16(&Pt[(sr + 8 * i) * PSTR + 4 * sc4], psrc + (size_t)(8 * i) * H);
        cp_commit();
    }

    float acc0 = 0.f, acc1 = 0.f, acc2 = 0.f, acc3 = 0.f;
    const int NT = H / KTILE;   // 12 tiles

    for (int it = 0; it < NT; it++) {
        if (it + 1 < NT) {
            int k0n = (it + 1) * KTILE;
            float* wdst = Ws + ((it + 1) & 1) * 32 * WSTR;
            float* pdst = Pt + ((it + 1) & 1) * 16 * PSTR;
            const float* wsrc = Wd + (size_t)(r0 + sr) * H + k0n + 4 * sc4;
            #pragma unroll
            for (int i = 0; i < 4; i++)
                cp16(&wdst[(sr + 8 * i) * WSTR + 4 * sc4], wsrc + (size_t)(8 * i) * H);
            const float* psrc = P + (size_t)(b0 + sr) * H + k0n + 4 * sc4;
            #pragma unroll
            for (int i = 0; i < 2; i++)
                cp16(&pdst[(sr + 8 * i) * PSTR + 4 * sc4], psrc + (size_t)(8 * i) * H);
            cp_commit();
            cp_wait<1>();
        } else {
            cp_wait<0>();
        }
        __syncthreads();

        const float* Wr = Ws + (it & 1) * 32 * WSTR + lane * WSTR;
        const float* Pb = Pt + (it & 1) * 16 * PSTR + (4 * wid) * PSTR;

        #pragma unroll
        for (int g = 0; g < KTILE / 4; g++) {
            float4 w  = *(const float4*)&Wr[4 * g];
            float4 p0 = *(const float4*)&Pb[4 * g];
            float4 p1 = *(const float4*)&Pb[PSTR + 4 * g];
            float4 p2 = *(const float4*)&Pb[2 * PSTR + 4 * g];
            float4 p3 = *(const float4*)&Pb[3 * PSTR + 4 * g];
            acc0 += w.x * p0.x + w.y * p0.y + w.z * p0.z + w.w * p0.w;
            acc1 += w.x * p1.x + w.y * p1.y + w.z * p1.z + w.w * p1.w;
            acc2 += w.x * p2.x + w.y * p2.y + w.z * p2.z + w.w * p2.w;
            acc3 += w.x * p3.x + w.y * p3.y + w.z * p3.z + w.w * p3.w;
        }
        __syncthreads();
    }

    // epilogue: tanh + bias -> Hs (row = lane; batches 4wid..4wid+3)
    float bdr = __ldg(&bd[r0 + lane]);
    Hs[(4 * wid + 0) * 34 + lane] = tanhf(acc0 + bdr);
    Hs[(4 * wid + 1) * 34 + lane] = tanhf(acc1 + bdr);
    Hs[(4 * wid + 2) * 34 + lane] = tanhf(acc2 + bdr);
    Hs[(4 * wid + 3) * 34 + lane] = tanhf(acc3 + bdr);
    __syncthreads();

    // fused classifier: warp wid handles batches 4wid..4wid+3 over 32 rows
    #pragma unroll
    for (int bb = 0; bb < 4; bb++) {
        int bl = 4 * wid + bb;
        float hv = Hs[bl * 34 + lane];
        for (int l = 0; l < nlab; l++) {
            float s = hv * __ldg(Wc + (size_t)l * H + r0 + lane);
            #pragma unroll
            for (int o = 16; o; o >>= 1) s += __shfl_xor_sync(0xffffffffu, s, o);
            if (lane == 0)
                atomicAdd(&out[outoff + (b0 + bl) * nlab + l], s);
        }
    }
}

// ---------------------------------------------------------------------------
extern "C" void kernel_launch(void* const* d_in, const int* in_sizes, int n_in,
                              void* d_out, int out_size) {
    const float* seq      = (const float*)d_in[0];
    const int*   rel_idx  = (const int*)d_in[1];
    const int*   rel_len  = (const int*)d_in[2];
    const int*   nov_idx  = (const int*)d_in[3];
    const int*   nov_len  = (const int*)d_in[4];
    const int*   dir_idx  = (const int*)d_in[5];
    const int*   dir_len  = (const int*)d_in[6];
    const float* rel_dW   = (const float*)d_in[7];
    const float* rel_db   = (const float*)d_in[8];
    const float* rel_cW   = (const float*)d_in[9];
    const float* rel_cb   = (const float*)d_in[10];
    const float* nov_dW   = (const float*)d_in[11];
    const float* nov_db   = (const float*)d_in[12];
    const float* nov_cW   = (const float*)d_in[13];
    const float* nov_cb   = (const float*)d_in[14];
    const float* dir_dW   = (const float*)d_in[15];
    const float* dir_db   = (const float*)d_in[16];
    const float* dir_cW   = (const float*)d_in[17];
    const float* dir_cb   = (const float*)d_in[18];
    float* out = (float*)d_out;

    attn_pool_kernel<<<dim3(B, 3, 3), 256>>>(seq, rel_idx, rel_len,
                                             nov_idx, nov_len, dir_idx, dir_len,
                                             rel_cb, nov_cb, dir_cb, out);
    dense_kernel<<<dim3(24, 4, 3), 128, DENSE_SMEM>>>(rel_dW, rel_db, nov_dW, nov_db,
                                                      dir_dW, dir_db,
                                                      rel_cW, nov_cW, dir_cW, out);
}